// round 1
// baseline (speedup 1.0000x reference)
#include <cuda_runtime.h>
#include <cstdint>

#define I_DIM 128
#define O_DIM 64
#define R_DIM 7
#define T_DIM 4
#define MAX_N 300000
#define RO (R_DIM * O_DIM)   // 448

// ---------------- scratch (device globals; no runtime allocation) ----------
__device__ float g_h[(size_t)MAX_N * RO];        // ~537.6 MB, per-(node,rel) messages
__device__ int   g_cnt[MAX_N * R_DIM];           // per-(dst,rel) edge counts
__device__ int   g_order[MAX_N];                 // nodes sorted by type (bucketed)
__device__ int   g_tcnt[T_DIM];
__device__ int   g_offsets[T_DIM + 1];
__device__ int   g_cursor[T_DIM];
__device__ int   g_blockBase[T_DIM + 1];

// ---------------- f32x2 packed-math helpers (Blackwell) ---------------------
__device__ __forceinline__ unsigned long long pack2(float a) {
    unsigned long long r;
    unsigned int u = __float_as_uint(a);
    asm("mov.b64 %0, {%1, %1};" : "=l"(r) : "r"(u));
    return r;
}
__device__ __forceinline__ void fma2(unsigned long long& d,
                                     unsigned long long a,
                                     unsigned long long b) {
    asm("fma.rn.f32x2 %0, %1, %2, %0;" : "+l"(d) : "l"(a), "l"(b));
}
__device__ __forceinline__ float2 unpack2(unsigned long long v) {
    float2 f;
    asm("mov.b64 {%0, %1}, %2;" : "=f"(f.x), "=f"(f.y) : "l"(v));
    return f;
}

// ---------------- small prep kernels ---------------------------------------
__global__ void edge_count_kernel(const int* __restrict__ ei,
                                  const int* __restrict__ etype, int E) {
    int e = blockIdx.x * 256 + threadIdx.x;
    if (e < E) {
        int dst = ei[E + e];
        int et  = etype[e];
        atomicAdd(&g_cnt[dst * R_DIM + et], 1);
    }
}

__global__ void type_hist_kernel(const int* __restrict__ nt, int n) {
    __shared__ int s[T_DIM];
    if (threadIdx.x < T_DIM) s[threadIdx.x] = 0;
    __syncthreads();
    int i = blockIdx.x * 256 + threadIdx.x;
    if (i < n) atomicAdd(&s[nt[i]], 1);
    __syncthreads();
    if (threadIdx.x < T_DIM) atomicAdd(&g_tcnt[threadIdx.x], s[threadIdx.x]);
}

__global__ void scan_kernel() {
    if (threadIdx.x == 0 && blockIdx.x == 0) {
        int off = 0, bb = 0;
        g_offsets[0] = 0;
        g_blockBase[0] = 0;
        for (int t = 0; t < T_DIM; t++) {
            int c = g_tcnt[t];
            g_cursor[t] = off;
            off += c;
            g_offsets[t + 1] = off;
            bb += (c + 127) >> 7;
            g_blockBase[t + 1] = bb;
        }
    }
}

__global__ void type_scatter_kernel(const int* __restrict__ nt, int n) {
    __shared__ int s_cnt[T_DIM];
    __shared__ int s_base[T_DIM];
    if (threadIdx.x < T_DIM) s_cnt[threadIdx.x] = 0;
    __syncthreads();
    int i = blockIdx.x * 256 + threadIdx.x;
    int t = 0, r = 0;
    bool valid = (i < n);
    if (valid) {
        t = nt[i];
        r = atomicAdd(&s_cnt[t], 1);
    }
    __syncthreads();
    if (threadIdx.x < T_DIM)
        s_base[threadIdx.x] = atomicAdd(&g_cursor[threadIdx.x], s_cnt[threadIdx.x]);
    __syncthreads();
    if (valid) g_order[s_base[t] + r] = i;
}

// ---------------- h = x @ W_rel[r] for all r, h layout [n][r][o] ------------
// BM=128, BN=64(=O), K=128 fully resident. 256 threads: tx in [0,8) owns 8
// outs (4 f32x2 pairs), ty in [0,32) owns 4 rows. Xs padded to 132 floats/row
// to break bank alignment on the strided a-loads.
#define XS_LD 132
#define SMEM_FLOATS (128 * XS_LD + 128 * 64)

extern "C" __global__ void __launch_bounds__(256, 2)
h_gemm_kernel(const float* __restrict__ x, const float* __restrict__ Wrel, int n) {
    extern __shared__ float smem[];
    float* Xs = smem;                 // [128][XS_LD]
    float* Ws = smem + 128 * XS_LD;   // [128][64]
    const int n0 = blockIdx.x * 128;
    const float4* x4 = (const float4*)x;

#pragma unroll
    for (int it = 0; it < 16; it++) {
        int idx = threadIdx.x + it * 256;
        int m = idx >> 5, kq = idx & 31;
        int node = n0 + m;
        float4 v = make_float4(0.f, 0.f, 0.f, 0.f);
        if (node < n) v = x4[(size_t)node * 32 + kq];
        *(float4*)&Xs[m * XS_LD + kq * 4] = v;
    }

    const int tx = threadIdx.x & 7, ty = threadIdx.x >> 3;
    const int tm0 = ty * 4, tn0 = tx * 8;

    for (int r = 0; r < R_DIM; r++) {
        __syncthreads();
        const float4* w4 = (const float4*)(Wrel + (size_t)r * (I_DIM * O_DIM));
#pragma unroll
        for (int it = 0; it < 8; it++) {
            int idx = threadIdx.x + it * 256;
            *(float4*)&Ws[idx * 4] = w4[idx];
        }
        __syncthreads();

        unsigned long long acc[4][4];
#pragma unroll
        for (int i = 0; i < 4; i++)
#pragma unroll
            for (int j = 0; j < 4; j++) acc[i][j] = 0ull;

#pragma unroll 8
        for (int k = 0; k < 128; k++) {
            unsigned long long B[4];
#pragma unroll
            for (int j = 0; j < 4; j++)
                B[j] = *(const unsigned long long*)&Ws[k * 64 + tn0 + 2 * j];
#pragma unroll
            for (int i = 0; i < 4; i++) {
                unsigned long long A = pack2(Xs[(tm0 + i) * XS_LD + k]);
                fma2(acc[i][0], A, B[0]);
                fma2(acc[i][1], A, B[1]);
                fma2(acc[i][2], A, B[2]);
                fma2(acc[i][3], A, B[3]);
            }
        }

#pragma unroll
        for (int i = 0; i < 4; i++) {
            int node = n0 + tm0 + i;
            if (node < n) {
                float2 p0 = unpack2(acc[i][0]), p1 = unpack2(acc[i][1]);
                float2 p2 = unpack2(acc[i][2]), p3 = unpack2(acc[i][3]);
                float* hp = g_h + (size_t)node * RO + r * O_DIM + tn0;
                *(float4*)hp       = make_float4(p0.x, p0.y, p1.x, p1.y);
                *(float4*)(hp + 4) = make_float4(p2.x, p2.y, p3.x, p3.y);
            }
        }
    }
}

// ---------------- root: out[n] = x[n] @ W_root[type[n]] + b_root[type[n]] ---
extern "C" __global__ void __launch_bounds__(256, 2)
root_gemm_kernel(const float* __restrict__ x, const float* __restrict__ Wroot,
                 const float* __restrict__ broot, float* __restrict__ out) {
    extern __shared__ float smem[];
    float* Xs = smem;
    float* Ws = smem + 128 * XS_LD;
    __shared__ int s_nid[128];

    int b = blockIdx.x;
    int t = -1, tile = 0;
#pragma unroll
    for (int tt = 0; tt < T_DIM; tt++) {
        int lo = g_blockBase[tt], hi = g_blockBase[tt + 1];
        if (t < 0 && b >= lo && b < hi) { t = tt; tile = b - lo; }
    }
    if (t < 0) return;
    int row0 = g_offsets[t] + tile * 128;
    int rowEnd = g_offsets[t + 1];

    for (int m = threadIdx.x; m < 128; m += 256) {
        int rr = row0 + m;
        s_nid[m] = (rr < rowEnd) ? g_order[rr] : -1;
    }
    __syncthreads();

    const float4* x4 = (const float4*)x;
#pragma unroll
    for (int it = 0; it < 16; it++) {
        int idx = threadIdx.x + it * 256;
        int m = idx >> 5, kq = idx & 31;
        int node = s_nid[m];
        float4 v = make_float4(0.f, 0.f, 0.f, 0.f);
        if (node >= 0) v = x4[(size_t)node * 32 + kq];
        *(float4*)&Xs[m * XS_LD + kq * 4] = v;
    }
    const float4* w4 = (const float4*)(Wroot + (size_t)t * (I_DIM * O_DIM));
#pragma unroll
    for (int it = 0; it < 8; it++) {
        int idx = threadIdx.x + it * 256;
        *(float4*)&Ws[idx * 4] = w4[idx];
    }
    __syncthreads();

    const int tx = threadIdx.x & 7, ty = threadIdx.x >> 3;
    const int tm0 = ty * 4, tn0 = tx * 8;

    unsigned long long acc[4][4];
#pragma unroll
    for (int i = 0; i < 4; i++)
#pragma unroll
        for (int j = 0; j < 4; j++) acc[i][j] = 0ull;

#pragma unroll 8
    for (int k = 0; k < 128; k++) {
        unsigned long long B[4];
#pragma unroll
        for (int j = 0; j < 4; j++)
            B[j] = *(const unsigned long long*)&Ws[k * 64 + tn0 + 2 * j];
#pragma unroll
        for (int i = 0; i < 4; i++) {
            unsigned long long A = pack2(Xs[(tm0 + i) * XS_LD + k]);
            fma2(acc[i][0], A, B[0]);
            fma2(acc[i][1], A, B[1]);
            fma2(acc[i][2], A, B[2]);
            fma2(acc[i][3], A, B[3]);
        }
    }

    float4 bias0 = *(const float4*)&broot[t * O_DIM + tn0];
    float4 bias1 = *(const float4*)&broot[t * O_DIM + tn0 + 4];
#pragma unroll
    for (int i = 0; i < 4; i++) {
        int node = s_nid[tm0 + i];
        if (node >= 0) {
            float2 p0 = unpack2(acc[i][0]), p1 = unpack2(acc[i][1]);
            float2 p2 = unpack2(acc[i][2]), p3 = unpack2(acc[i][3]);
            float* op = out + (size_t)node * O_DIM + tn0;
            *(float4*)op = make_float4(p0.x + bias0.x, p0.y + bias0.y,
                                       p1.x + bias0.z, p1.y + bias0.w);
            *(float4*)(op + 4) = make_float4(p2.x + bias1.x, p2.y + bias1.y,
                                             p3.x + bias1.z, p3.y + bias1.w);
        }
    }
}

// ---------------- edge scatter: out[dst] += h[src,et] / cnt[dst,et] ---------
// 16 lanes per edge; each lane moves one float4 (64 floats total) and issues
// a vectorized red.global.add.v4.f32.
__global__ void __launch_bounds__(256)
edge_scatter_kernel(const int* __restrict__ ei, const int* __restrict__ etype,
                    float* __restrict__ out, int E) {
    long long tid = (long long)blockIdx.x * 256 + threadIdx.x;
    int lane16 = (int)(tid & 15);
    long long e = tid >> 4;
    if (e >= E) return;
    int src = __ldg(&ei[e]);
    int dst = __ldg(&ei[E + e]);
    int et  = __ldg(&etype[e]);
    int c   = __ldg(&g_cnt[dst * R_DIM + et]);
    float inv = 1.0f / (float)c;   // c >= 1: this edge was counted
    const float4* hp = (const float4*)(g_h + (size_t)src * RO + (size_t)et * O_DIM);
    float4 v = __ldg(&hp[lane16]);
    float* op = out + (size_t)dst * O_DIM + lane16 * 4;
    asm volatile("red.global.add.v4.f32 [%0], {%1, %2, %3, %4};"
                 :: "l"(op), "f"(v.x * inv), "f"(v.y * inv),
                    "f"(v.z * inv), "f"(v.w * inv)
                 : "memory");
}

// ---------------- launch ----------------------------------------------------
extern "C" void kernel_launch(void* const* d_in, const int* in_sizes, int n_in,
                              void* d_out, int out_size) {
    const float* x     = (const float*)d_in[0];
    const int*   ei    = (const int*)d_in[1];
    const int*   et    = (const int*)d_in[2];
    const int*   nt    = (const int*)d_in[3];
    const float* Wrel  = (const float*)d_in[4];
    const float* Wroot = (const float*)d_in[5];
    const float* broot = (const float*)d_in[6];
    float*       out   = (float*)d_out;

    int n = in_sizes[0] / I_DIM;
    int E = in_sizes[2];

    void *p_cnt = nullptr, *p_tcnt = nullptr;
    cudaGetSymbolAddress(&p_cnt, g_cnt);
    cudaGetSymbolAddress(&p_tcnt, g_tcnt);
    cudaMemsetAsync(p_cnt, 0, sizeof(int) * (size_t)n * R_DIM, 0);
    cudaMemsetAsync(p_tcnt, 0, sizeof(int) * T_DIM, 0);

    edge_count_kernel<<<(E + 255) / 256, 256>>>(ei, et, E);
    type_hist_kernel<<<(n + 255) / 256, 256>>>(nt, n);
    scan_kernel<<<1, 32>>>();
    type_scatter_kernel<<<(n + 255) / 256, 256>>>(nt, n);

    int smem_bytes = SMEM_FLOATS * (int)sizeof(float);
    cudaFuncSetAttribute(h_gemm_kernel,
                         cudaFuncAttributeMaxDynamicSharedMemorySize, smem_bytes);
    cudaFuncSetAttribute(root_gemm_kernel,
                         cudaFuncAttributeMaxDynamicSharedMemorySize, smem_bytes);

    int gemm_blocks = (n + 127) / 128;
    h_gemm_kernel<<<gemm_blocks, 256, smem_bytes>>>(x, Wrel, n);
    root_gemm_kernel<<<gemm_blocks + T_DIM, 256, smem_bytes>>>(x, Wroot, broot, out);

    long long sc_threads = (long long)E * 16;
    int sc_blocks = (int)((sc_threads + 255) / 256);
    edge_scatter_kernel<<<sc_blocks, 256>>>(ei, et, out, E);
}

// round 13
// speedup vs baseline: 1.8547x; 1.8547x over previous
#include <cuda_runtime.h>
#include <cuda_bf16.h>
#include <cstdint>

#define I_DIM 128
#define O_DIM 64
#define R_DIM 7
#define T_DIM 4
#define MAX_N 300000
#define RO (R_DIM * O_DIM)   // 448

// ---------------- scratch (device globals; no runtime allocation) ----------
__device__ float         g_h[(size_t)MAX_N * RO];     // ~537.6 MB
__device__ int           g_cnt[MAX_N * R_DIM];
__device__ int           g_order[MAX_N];
__device__ int           g_tcnt[T_DIM];
__device__ int           g_offsets[T_DIM + 1];
__device__ int           g_cursor[T_DIM];
__device__ int           g_blockBase[T_DIM + 1];
__device__ __nv_bfloat16 g_xhi[(size_t)MAX_N * I_DIM];   // 76.8 MB
__device__ __nv_bfloat16 g_xlo[(size_t)MAX_N * I_DIM];   // 76.8 MB
__device__ __nv_bfloat16 g_whi[R_DIM * O_DIM * I_DIM];   // [r][o][i] K-major
__device__ __nv_bfloat16 g_wlo[R_DIM * O_DIM * I_DIM];
__device__ __nv_bfloat16 g_rwhi[T_DIM * O_DIM * I_DIM];
__device__ __nv_bfloat16 g_rwlo[T_DIM * O_DIM * I_DIM];

// ---------------- warp-MMA helpers (sm_80+ base features, OK on sm_103) -----
__device__ __forceinline__ uint32_t smem_u32(const void* p) {
    uint32_t a;
    asm("{ .reg .u64 t; cvta.to.shared.u64 t, %1; cvt.u32.u64 %0, t; }"
        : "=r"(a) : "l"(p));
    return a;
}
__device__ __forceinline__ void ldsm4(uint32_t* r, uint32_t addr) {
    asm volatile("ldmatrix.sync.aligned.m8n8.x4.shared.b16 {%0,%1,%2,%3}, [%4];"
                 : "=r"(r[0]), "=r"(r[1]), "=r"(r[2]), "=r"(r[3]) : "r"(addr));
}
// NON-trans x2: B stored [n][k] (k contiguous) IS col-major k x n; plain
// ldmatrix yields the b-fragment (thread t: consecutive k at fixed n=t/4).
__device__ __forceinline__ void ldsm2(uint32_t* r, uint32_t addr) {
    asm volatile("ldmatrix.sync.aligned.m8n8.x2.shared.b16 {%0,%1}, [%2];"
                 : "=r"(r[0]), "=r"(r[1]) : "r"(addr));
}
__device__ __forceinline__ void mma16816(float* c, const uint32_t* a, const uint32_t* b) {
    asm volatile(
        "mma.sync.aligned.m16n8k16.row.col.f32.bf16.bf16.f32 "
        "{%0,%1,%2,%3}, {%4,%5,%6,%7}, {%8,%9}, {%0,%1,%2,%3};"
        : "+f"(c[0]), "+f"(c[1]), "+f"(c[2]), "+f"(c[3])
        : "r"(a[0]), "r"(a[1]), "r"(a[2]), "r"(a[3]), "r"(b[0]), "r"(b[1]));
}

// smem layout (bytes): rows are 128 bf16 = 256B data; pitch 272 = 256+16 pad.
// 272/4 = 68 words == 4 mod 32 banks -> ldmatrix 8-row fetches conflict-free.
#define A_PITCH 272
#define SM_A_HI 0
#define SM_A_LO 34816              // 128*272
#define SM_B_HI 69632
#define SM_B_LO 87040              // +64*272
#define SMEM_DYN 104448            // +64*272

// ---------------- conversion kernels ----------------------------------------
__global__ void convert_x_kernel(const float* __restrict__ x, int total2) {
    int i = blockIdx.x * 256 + threadIdx.x;
    if (i < total2) {
        float2 v = ((const float2*)x)[i];
        __nv_bfloat16 h0 = __float2bfloat16(v.x);
        __nv_bfloat16 h1 = __float2bfloat16(v.y);
        __nv_bfloat162 hh; hh.x = h0; hh.y = h1;
        __nv_bfloat162 ll;
        ll.x = __float2bfloat16(v.x - __bfloat162float(h0));
        ll.y = __float2bfloat16(v.y - __bfloat162float(h1));
        ((__nv_bfloat162*)g_xhi)[i] = hh;
        ((__nv_bfloat162*)g_xlo)[i] = ll;
    }
}

__global__ void convert_w_kernel(const float* __restrict__ Wrel,
                                 const float* __restrict__ Wroot) {
    int i = blockIdx.x * 256 + threadIdx.x;
    if (i >= (R_DIM + T_DIM) * O_DIM * I_DIM) return;
    int grp = i >> 13;            // 8192 = 64*128
    int rem = i & 8191;
    int nrow = rem >> 7;          // O index
    int k = rem & 127;            // I index
    float v;
    if (grp < R_DIM) v = Wrel[((size_t)grp * I_DIM + k) * O_DIM + nrow];
    else             v = Wroot[((size_t)(grp - R_DIM) * I_DIM + k) * O_DIM + nrow];
    __nv_bfloat16 h = __float2bfloat16(v);
    __nv_bfloat16 l = __float2bfloat16(v - __bfloat162float(h));
    if (grp < R_DIM) { g_whi[i] = h; g_wlo[i] = l; }
    else { g_rwhi[(grp - R_DIM) * 8192 + rem] = h; g_rwlo[(grp - R_DIM) * 8192 + rem] = l; }
}

// ---------------- small prep kernels ---------------------------------------
__global__ void edge_count_kernel(const int* __restrict__ ei,
                                  const int* __restrict__ etype, int E) {
    int e = blockIdx.x * 256 + threadIdx.x;
    if (e < E) atomicAdd(&g_cnt[ei[E + e] * R_DIM + etype[e]], 1);
}

__global__ void type_hist_kernel(const int* __restrict__ nt, int n) {
    __shared__ int s[T_DIM];
    if (threadIdx.x < T_DIM) s[threadIdx.x] = 0;
    __syncthreads();
    int i = blockIdx.x * 256 + threadIdx.x;
    if (i < n) atomicAdd(&s[nt[i]], 1);
    __syncthreads();
    if (threadIdx.x < T_DIM) atomicAdd(&g_tcnt[threadIdx.x], s[threadIdx.x]);
}

__global__ void scan_kernel() {
    if (threadIdx.x == 0 && blockIdx.x == 0) {
        int off = 0, bb = 0;
        g_offsets[0] = 0;
        g_blockBase[0] = 0;
        for (int t = 0; t < T_DIM; t++) {
            int c = g_tcnt[t];
            g_cursor[t] = off;
            off += c;
            g_offsets[t + 1] = off;
            bb += (c + 127) >> 7;
            g_blockBase[t + 1] = bb;
        }
    }
}

__global__ void type_scatter_kernel(const int* __restrict__ nt, int n) {
    __shared__ int s_cnt[T_DIM];
    __shared__ int s_base[T_DIM];
    if (threadIdx.x < T_DIM) s_cnt[threadIdx.x] = 0;
    __syncthreads();
    int i = blockIdx.x * 256 + threadIdx.x;
    int t = 0, r = 0;
    bool valid = (i < n);
    if (valid) { t = nt[i]; r = atomicAdd(&s_cnt[t], 1); }
    __syncthreads();
    if (threadIdx.x < T_DIM)
        s_base[threadIdx.x] = atomicAdd(&g_cursor[threadIdx.x], s_cnt[threadIdx.x]);
    __syncthreads();
    if (valid) g_order[s_base[t] + r] = i;
}

// ---------------- shared device helpers for the MMA GEMMs -------------------
// Per block: 128 M-rows x 64 N-cols x K=128. 8 warps: (wid&3)=M-group of 32
// rows, (wid>>2)=N-half of 32 cols. Per warp: 2 m16 tiles x 4 n8 tiles.
// fp32 emulation: acc += Ahi*Bhi + Ahi*Blo + Alo*Bhi (bf16 mma, f32 accum).
struct Frag { float acc[2][4][4]; };

__device__ __forceinline__ void mma_tile_compute(Frag& F, uint32_t sb,
                                                 int mgroup, int nhalf, int lane) {
#pragma unroll
    for (int mt = 0; mt < 2; mt++)
#pragma unroll
        for (int nt = 0; nt < 4; nt++)
#pragma unroll
            for (int q = 0; q < 4; q++) F.acc[mt][nt][q] = 0.f;

    const int lr = lane & 7, g = lane >> 3;
#pragma unroll
    for (int ks = 0; ks < 8; ks++) {
        const int k0 = ks * 16;
        uint32_t ahi[2][4], alo[2][4];
#pragma unroll
        for (int mt = 0; mt < 2; mt++) {
            int row = mgroup * 32 + mt * 16 + lr + (g & 1) * 8;
            uint32_t aaddr = sb + (uint32_t)row * A_PITCH + (uint32_t)(k0 + (g >> 1) * 8) * 2;
            ldsm4(ahi[mt], aaddr + SM_A_HI);
            ldsm4(alo[mt], aaddr + SM_A_LO);
        }
        uint32_t bhi[4][2], blo[4][2];
#pragma unroll
        for (int nt = 0; nt < 4; nt++) {
            int nrow = nhalf * 32 + nt * 8 + lr;
            uint32_t baddr = sb + (uint32_t)nrow * A_PITCH + (uint32_t)(k0 + (g & 1) * 8) * 2;
            ldsm2(bhi[nt], baddr + SM_B_HI);
            ldsm2(blo[nt], baddr + SM_B_LO);
        }
#pragma unroll
        for (int mt = 0; mt < 2; mt++)
#pragma unroll
            for (int nt = 0; nt < 4; nt++) {
                mma16816(F.acc[mt][nt], ahi[mt], bhi[nt]);
                mma16816(F.acc[mt][nt], ahi[mt], blo[nt]);
                mma16816(F.acc[mt][nt], alo[mt], bhi[nt]);
            }
    }
}

// ---------------- h = x @ W_rel[r] for all r --------------------------------
extern "C" __global__ void __launch_bounds__(256, 2)
h_mma_kernel(int n) {
    extern __shared__ __align__(16) char sm[];
    const uint32_t sb = smem_u32(sm);
    const int tid = threadIdx.x, wid = tid >> 5, lane = tid & 31;
    const int mgroup = wid & 3, nhalf = wid >> 2;
    const int n0 = blockIdx.x * 128;

    // Load A (x hi/lo): 128 rows x 16 chunks of 16B, pitch 272
#pragma unroll
    for (int it = 0; it < 8; it++) {
        int idx = tid + it * 256;           // 0..2047
        int row = idx >> 4, c = idx & 15;
        int node = n0 + row;
        uint4 vh = make_uint4(0, 0, 0, 0), vl = vh;
        if (node < n) {
            vh = ((const uint4*)(g_xhi + (size_t)node * I_DIM))[c];
            vl = ((const uint4*)(g_xlo + (size_t)node * I_DIM))[c];
        }
        *(uint4*)(sm + SM_A_HI + row * A_PITCH + c * 16) = vh;
        *(uint4*)(sm + SM_A_LO + row * A_PITCH + c * 16) = vl;
    }

    Frag F;
    for (int r = 0; r < R_DIM; r++) {
        __syncthreads();
        // Load B_r (W hi/lo): 64 rows x 16 chunks, pitch 272
#pragma unroll
        for (int it = 0; it < 4; it++) {
            int idx = tid + it * 256;       // 0..1023
            int nr = idx >> 4, c = idx & 15;
            uint4 vh = ((const uint4*)(g_whi + ((size_t)r * O_DIM + nr) * I_DIM))[c];
            uint4 vl = ((const uint4*)(g_wlo + ((size_t)r * O_DIM + nr) * I_DIM))[c];
            *(uint4*)(sm + SM_B_HI + nr * A_PITCH + c * 16) = vh;
            *(uint4*)(sm + SM_B_LO + nr * A_PITCH + c * 16) = vl;
        }
        __syncthreads();

        mma_tile_compute(F, sb, mgroup, nhalf, lane);

        // epilogue: write h[node][r][col]
#pragma unroll
        for (int mt = 0; mt < 2; mt++) {
            int row = mgroup * 32 + mt * 16 + (lane >> 2);
#pragma unroll
            for (int nt = 0; nt < 4; nt++) {
                int col = nhalf * 32 + nt * 8 + (lane & 3) * 2;
                int nodeA = n0 + row, nodeB = n0 + row + 8;
                if (nodeA < n)
                    *(float2*)(g_h + (size_t)nodeA * RO + r * O_DIM + col) =
                        make_float2(F.acc[mt][nt][0], F.acc[mt][nt][1]);
                if (nodeB < n)
                    *(float2*)(g_h + (size_t)nodeB * RO + r * O_DIM + col) =
                        make_float2(F.acc[mt][nt][2], F.acc[mt][nt][3]);
            }
        }
    }
}

// ---------------- root: out = x @ W_root[type] + b_root[type] ---------------
extern "C" __global__ void __launch_bounds__(256, 2)
root_mma_kernel(const float* __restrict__ broot, float* __restrict__ out) {
    extern __shared__ __align__(16) char sm[];
    __shared__ int s_nid[128];
    const uint32_t sb = smem_u32(sm);
    const int tid = threadIdx.x, wid = tid >> 5, lane = tid & 31;
    const int mgroup = wid & 3, nhalf = wid >> 2;

    int b = blockIdx.x;
    int t = -1, tile = 0;
#pragma unroll
    for (int tt = 0; tt < T_DIM; tt++) {
        int lo = g_blockBase[tt], hi = g_blockBase[tt + 1];
        if (t < 0 && b >= lo && b < hi) { t = tt; tile = b - lo; }
    }
    if (t < 0) return;
    int row0 = g_offsets[t] + tile * 128;
    int rowEnd = g_offsets[t + 1];

    if (tid < 128) {
        int rr = row0 + tid;
        s_nid[tid] = (rr < rowEnd) ? g_order[rr] : -1;
    }
    __syncthreads();

#pragma unroll
    for (int it = 0; it < 8; it++) {
        int idx = tid + it * 256;
        int row = idx >> 4, c = idx & 15;
        int node = s_nid[row];
        uint4 vh = make_uint4(0, 0, 0, 0), vl = vh;
        if (node >= 0) {
            vh = ((const uint4*)(g_xhi + (size_t)node * I_DIM))[c];
            vl = ((const uint4*)(g_xlo + (size_t)node * I_DIM))[c];
        }
        *(uint4*)(sm + SM_A_HI + row * A_PITCH + c * 16) = vh;
        *(uint4*)(sm + SM_A_LO + row * A_PITCH + c * 16) = vl;
    }
#pragma unroll
    for (int it = 0; it < 4; it++) {
        int idx = tid + it * 256;
        int nr = idx >> 4, c = idx & 15;
        uint4 vh = ((const uint4*)(g_rwhi + ((size_t)t * O_DIM + nr) * I_DIM))[c];
        uint4 vl = ((const uint4*)(g_rwlo + ((size_t)t * O_DIM + nr) * I_DIM))[c];
        *(uint4*)(sm + SM_B_HI + nr * A_PITCH + c * 16) = vh;
        *(uint4*)(sm + SM_B_LO + nr * A_PITCH + c * 16) = vl;
    }
    __syncthreads();

    Frag F;
    mma_tile_compute(F, sb, mgroup, nhalf, lane);

#pragma unroll
    for (int mt = 0; mt < 2; mt++) {
        int row = mgroup * 32 + mt * 16 + (lane >> 2);
#pragma unroll
        for (int nt = 0; nt < 4; nt++) {
            int col = nhalf * 32 + nt * 8 + (lane & 3) * 2;
            float2 bias = *(const float2*)(broot + (size_t)t * O_DIM + col);
            int nodeA = s_nid[row], nodeB = s_nid[row + 8];
            if (nodeA >= 0)
                *(float2*)(out + (size_t)nodeA * O_DIM + col) =
                    make_float2(F.acc[mt][nt][0] + bias.x, F.acc[mt][nt][1] + bias.y);
            if (nodeB >= 0)
                *(float2*)(out + (size_t)nodeB * O_DIM + col) =
                    make_float2(F.acc[mt][nt][2] + bias.x, F.acc[mt][nt][3] + bias.y);
        }
    }
}

// ---------------- edge scatter: out[dst] += h[src,et] / cnt[dst,et] ---------
__global__ void __launch_bounds__(256)
edge_scatter_kernel(const int* __restrict__ ei, const int* __restrict__ etype,
                    float* __restrict__ out, int E) {
    long long tid = (long long)blockIdx.x * 256 + threadIdx.x;
    int lane16 = (int)(tid & 15);
    long long e = tid >> 4;
    if (e >= E) return;
    int src = __ldg(&ei[e]);
    int dst = __ldg(&ei[E + e]);
    int et  = __ldg(&etype[e]);
    int c   = __ldg(&g_cnt[dst * R_DIM + et]);
    float inv = 1.0f / (float)c;
    const float4* hp = (const float4*)(g_h + (size_t)src * RO + (size_t)et * O_DIM);
    float4 v = __ldg(&hp[lane16]);
    float* op = out + (size_t)dst * O_DIM + lane16 * 4;
    asm volatile("red.global.add.v4.f32 [%0], {%1, %2, %3, %4};"
                 :: "l"(op), "f"(v.x * inv), "f"(v.y * inv),
                    "f"(v.z * inv), "f"(v.w * inv)
                 : "memory");
}

// ---------------- launch ----------------------------------------------------
extern "C" void kernel_launch(void* const* d_in, const int* in_sizes, int n_in,
                              void* d_out, int out_size) {
    const float* x     = (const float*)d_in[0];
    const int*   ei    = (const int*)d_in[1];
    const int*   et    = (const int*)d_in[2];
    const int*   nt    = (const int*)d_in[3];
    const float* Wrel  = (const float*)d_in[4];
    const float* Wroot = (const float*)d_in[5];
    const float* broot = (const float*)d_in[6];
    float*       out   = (float*)d_out;

    int n = in_sizes[0] / I_DIM;
    int E = in_sizes[2];

    void *p_cnt = nullptr, *p_tcnt = nullptr;
    cudaGetSymbolAddress(&p_cnt, g_cnt);
    cudaGetSymbolAddress(&p_tcnt, g_tcnt);
    cudaMemsetAsync(p_cnt, 0, sizeof(int) * (size_t)n * R_DIM, 0);
    cudaMemsetAsync(p_tcnt, 0, sizeof(int) * T_DIM, 0);

    cudaFuncSetAttribute(h_mma_kernel,
                         cudaFuncAttributeMaxDynamicSharedMemorySize, SMEM_DYN);
    cudaFuncSetAttribute(root_mma_kernel,
                         cudaFuncAttributeMaxDynamicSharedMemorySize, SMEM_DYN);

    int total2 = n * (I_DIM / 2);
    convert_x_kernel<<<(total2 + 255) / 256, 256>>>(x, total2);
    convert_w_kernel<<<((R_DIM + T_DIM) * O_DIM * I_DIM + 255) / 256, 256>>>(Wrel, Wroot);
    edge_count_kernel<<<(E + 255) / 256, 256>>>(ei, et, E);

    int gemm_blocks = (n + 127) / 128;
    h_mma_kernel<<<gemm_blocks, 256, SMEM_DYN>>>(n);   // 6th op -> ncu -s 5 captures this

    type_hist_kernel<<<(n + 255) / 256, 256>>>(nt, n);
    scan_kernel<<<1, 32>>>();
    type_scatter_kernel<<<(n + 255) / 256, 256>>>(nt, n);
    root_mma_kernel<<<gemm_blocks + T_DIM, 256, SMEM_DYN>>>(broot, out);

    long long sc_threads = (long long)E * 16;
    int sc_blocks = (int)((sc_threads + 255) / 256);
    edge_scatter_kernel<<<sc_blocks, 256>>>(ei, et, out, E);
}

// round 15
// speedup vs baseline: 1.8846x; 1.0161x over previous
#include <cuda_runtime.h>
#include <cuda_bf16.h>
#include <cstdint>

#define I_DIM 128
#define O_DIM 64
#define R_DIM 7
#define T_DIM 4
#define MAX_N 300000
#define MAX_E 4000000
#define RO (R_DIM * O_DIM)   // 448

// ---------------- scratch (device globals; no runtime allocation) ----------
__device__ float         g_h[(size_t)MAX_N * RO];     // ~537.6 MB
__device__ int           g_cnt[MAX_N * R_DIM];
__device__ int           g_order[MAX_N];
__device__ int           g_tcnt[T_DIM];
__device__ int           g_offsets[T_DIM + 1];
__device__ int           g_cursor[T_DIM];
__device__ int           g_blockBase[T_DIM + 1];
__device__ int           g_dstcnt[MAX_N];             // per-dst edge count
__device__ int           g_dstoff[MAX_N];             // exclusive prefix
__device__ int           g_dstcur[MAX_N];             // scatter cursors
__device__ int           g_bsum[1024];                // block sums for scan
__device__ int           g_sorted[MAX_E];             // (et<<20)|src, dst-sorted
__device__ __nv_bfloat16 g_xhi[(size_t)MAX_N * I_DIM];
__device__ __nv_bfloat16 g_xlo[(size_t)MAX_N * I_DIM];
__device__ __nv_bfloat16 g_whi[R_DIM * O_DIM * I_DIM];   // [r][o][i] K-major
__device__ __nv_bfloat16 g_wlo[R_DIM * O_DIM * I_DIM];
__device__ __nv_bfloat16 g_rwhi[T_DIM * O_DIM * I_DIM];
__device__ __nv_bfloat16 g_rwlo[T_DIM * O_DIM * I_DIM];

// ---------------- warp-MMA helpers (sm_80+ base features, OK on sm_103) -----
__device__ __forceinline__ uint32_t smem_u32(const void* p) {
    uint32_t a;
    asm("{ .reg .u64 t; cvta.to.shared.u64 t, %1; cvt.u32.u64 %0, t; }"
        : "=r"(a) : "l"(p));
    return a;
}
__device__ __forceinline__ void ldsm4(uint32_t* r, uint32_t addr) {
    asm volatile("ldmatrix.sync.aligned.m8n8.x4.shared.b16 {%0,%1,%2,%3}, [%4];"
                 : "=r"(r[0]), "=r"(r[1]), "=r"(r[2]), "=r"(r[3]) : "r"(addr));
}
// NON-trans x2: B stored [n][k] (k contiguous) IS col-major k x n; plain
// ldmatrix yields the b-fragment (thread t: consecutive k at fixed n=t/4).
__device__ __forceinline__ void ldsm2(uint32_t* r, uint32_t addr) {
    asm volatile("ldmatrix.sync.aligned.m8n8.x2.shared.b16 {%0,%1}, [%2];"
                 : "=r"(r[0]), "=r"(r[1]) : "r"(addr));
}
__device__ __forceinline__ void mma16816(float* c, const uint32_t* a, const uint32_t* b) {
    asm volatile(
        "mma.sync.aligned.m16n8k16.row.col.f32.bf16.bf16.f32 "
        "{%0,%1,%2,%3}, {%4,%5,%6,%7}, {%8,%9}, {%0,%1,%2,%3};"
        : "+f"(c[0]), "+f"(c[1]), "+f"(c[2]), "+f"(c[3])
        : "r"(a[0]), "r"(a[1]), "r"(a[2]), "r"(a[3]), "r"(b[0]), "r"(b[1]));
}

// smem layout (bytes): rows are 128 bf16 = 256B data; pitch 272 = 256+16 pad.
#define A_PITCH 272
#define SM_A_HI 0
#define SM_A_LO 34816              // 128*272
#define SM_B_HI 69632
#define SM_B_LO 87040              // +64*272
#define SMEM_DYN 104448            // +64*272

// ---------------- conversion kernels ----------------------------------------
__global__ void convert_x_kernel(const float* __restrict__ x, int total2) {
    int i = blockIdx.x * 256 + threadIdx.x;
    if (i < total2) {
        float2 v = ((const float2*)x)[i];
        __nv_bfloat16 h0 = __float2bfloat16(v.x);
        __nv_bfloat16 h1 = __float2bfloat16(v.y);
        __nv_bfloat162 hh; hh.x = h0; hh.y = h1;
        __nv_bfloat162 ll;
        ll.x = __float2bfloat16(v.x - __bfloat162float(h0));
        ll.y = __float2bfloat16(v.y - __bfloat162float(h1));
        ((__nv_bfloat162*)g_xhi)[i] = hh;
        ((__nv_bfloat162*)g_xlo)[i] = ll;
    }
}

__global__ void convert_w_kernel(const float* __restrict__ Wrel,
                                 const float* __restrict__ Wroot) {
    int i = blockIdx.x * 256 + threadIdx.x;
    if (i >= (R_DIM + T_DIM) * O_DIM * I_DIM) return;
    int grp = i >> 13;            // 8192 = 64*128
    int rem = i & 8191;
    int nrow = rem >> 7;          // O index
    int k = rem & 127;            // I index
    float v;
    if (grp < R_DIM) v = Wrel[((size_t)grp * I_DIM + k) * O_DIM + nrow];
    else             v = Wroot[((size_t)(grp - R_DIM) * I_DIM + k) * O_DIM + nrow];
    __nv_bfloat16 h = __float2bfloat16(v);
    __nv_bfloat16 l = __float2bfloat16(v - __bfloat162float(h));
    if (grp < R_DIM) { g_whi[i] = h; g_wlo[i] = l; }
    else { g_rwhi[(grp - R_DIM) * 8192 + rem] = h; g_rwlo[(grp - R_DIM) * 8192 + rem] = l; }
}

// ---------------- small prep kernels ---------------------------------------
__global__ void edge_count_kernel(const int* __restrict__ ei,
                                  const int* __restrict__ etype, int E) {
    int e = blockIdx.x * 256 + threadIdx.x;
    if (e < E) {
        int dst = ei[E + e];
        atomicAdd(&g_cnt[dst * R_DIM + etype[e]], 1);
        atomicAdd(&g_dstcnt[dst], 1);
    }
}

__global__ void type_hist_kernel(const int* __restrict__ nt, int n) {
    __shared__ int s[T_DIM];
    if (threadIdx.x < T_DIM) s[threadIdx.x] = 0;
    __syncthreads();
    int i = blockIdx.x * 256 + threadIdx.x;
    if (i < n) atomicAdd(&s[nt[i]], 1);
    __syncthreads();
    if (threadIdx.x < T_DIM) atomicAdd(&g_tcnt[threadIdx.x], s[threadIdx.x]);
}

__global__ void scan_kernel() {
    if (threadIdx.x == 0 && blockIdx.x == 0) {
        int off = 0, bb = 0;
        g_offsets[0] = 0;
        g_blockBase[0] = 0;
        for (int t = 0; t < T_DIM; t++) {
            int c = g_tcnt[t];
            g_cursor[t] = off;
            off += c;
            g_offsets[t + 1] = off;
            bb += (c + 127) >> 7;
            g_blockBase[t + 1] = bb;
        }
    }
}

__global__ void type_scatter_kernel(const int* __restrict__ nt, int n) {
    __shared__ int s_cnt[T_DIM];
    __shared__ int s_base[T_DIM];
    if (threadIdx.x < T_DIM) s_cnt[threadIdx.x] = 0;
    __syncthreads();
    int i = blockIdx.x * 256 + threadIdx.x;
    int t = 0, r = 0;
    bool valid = (i < n);
    if (valid) { t = nt[i]; r = atomicAdd(&s_cnt[t], 1); }
    __syncthreads();
    if (threadIdx.x < T_DIM)
        s_base[threadIdx.x] = atomicAdd(&g_cursor[threadIdx.x], s_cnt[threadIdx.x]);
    __syncthreads();
    if (valid) g_order[s_base[t] + r] = i;
}

// ---------------- dst-CSR: block scan over per-dst counts -------------------
__global__ void scan_blocks_kernel(int n) {
    __shared__ int wsum[16];
    int i = blockIdx.x * 512 + threadIdx.x;
    int lane = threadIdx.x & 31, wid = threadIdx.x >> 5;
    int v = (i < n) ? g_dstcnt[i] : 0;
    int x = v;
#pragma unroll
    for (int d = 1; d < 32; d <<= 1) {
        int y = __shfl_up_sync(0xFFFFFFFF, x, d);
        if (lane >= d) x += y;
    }
    if (lane == 31) wsum[wid] = x;
    __syncthreads();
    if (wid == 0) {
        int s = (lane < 16) ? wsum[lane] : 0;
#pragma unroll
        for (int d = 1; d < 16; d <<= 1) {
            int y = __shfl_up_sync(0xFFFFFFFF, s, d);
            if (lane >= d) s += y;
        }
        if (lane < 16) wsum[lane] = s;
    }
    __syncthreads();
    int base = (wid > 0) ? wsum[wid - 1] : 0;
    if (i < n) g_dstoff[i] = base + x - v;          // exclusive within block
    if (threadIdx.x == 511) g_bsum[blockIdx.x] = base + x;  // block total
}

__global__ void scan_top_kernel(int nblk) {
    __shared__ int wsum[32];
    int i = threadIdx.x;                   // single block, 1024 threads
    int lane = i & 31, wid = i >> 5;
    int v = (i < nblk) ? g_bsum[i] : 0;
    int x = v;
#pragma unroll
    for (int d = 1; d < 32; d <<= 1) {
        int y = __shfl_up_sync(0xFFFFFFFF, x, d);
        if (lane >= d) x += y;
    }
    if (lane == 31) wsum[wid] = x;
    __syncthreads();
    if (wid == 0) {
        int s = wsum[lane];
#pragma unroll
        for (int d = 1; d < 32; d <<= 1) {
            int y = __shfl_up_sync(0xFFFFFFFF, s, d);
            if (lane >= d) s += y;
        }
        wsum[lane] = s;
    }
    __syncthreads();
    int base = (wid > 0) ? wsum[wid - 1] : 0;
    if (i < nblk) g_bsum[i] = base + x - v;         // exclusive block offsets
}

__global__ void scan_add_kernel(int n) {
    int i = blockIdx.x * 512 + threadIdx.x;
    if (i < n) {
        int off = g_dstoff[i] + g_bsum[i >> 9];
        g_dstoff[i] = off;
        g_dstcur[i] = off;
    }
}

__global__ void sort_scatter_kernel(const int* __restrict__ ei,
                                    const int* __restrict__ etype, int E) {
    int e = blockIdx.x * 256 + threadIdx.x;
    if (e < E) {
        int dst = ei[E + e];
        int pos = atomicAdd(&g_dstcur[dst], 1);
        g_sorted[pos] = (etype[e] << 20) | ei[e];   // src < 2^20 fits
    }
}

// ---------------- shared device helpers for the MMA GEMMs -------------------
// Per block: 128 M-rows x 64 N-cols x K=128. 8 warps: (wid&3)=M-group of 32
// rows, (wid>>2)=N-half of 32 cols. Per warp: 2 m16 tiles x 4 n8 tiles.
// fp32 emulation: acc += Ahi*Bhi + Ahi*Blo + Alo*Bhi (bf16 mma, f32 accum).
struct Frag { float acc[2][4][4]; };

__device__ __forceinline__ void mma_tile_compute(Frag& F, uint32_t sb,
                                                 int mgroup, int nhalf, int lane) {
#pragma unroll
    for (int mt = 0; mt < 2; mt++)
#pragma unroll
        for (int nt = 0; nt < 4; nt++)
#pragma unroll
            for (int q = 0; q < 4; q++) F.acc[mt][nt][q] = 0.f;

    const int lr = lane & 7, g = lane >> 3;
#pragma unroll
    for (int ks = 0; ks < 8; ks++) {
        const int k0 = ks * 16;
        uint32_t ahi[2][4], alo[2][4];
#pragma unroll
        for (int mt = 0; mt < 2; mt++) {
            int row = mgroup * 32 + mt * 16 + lr + (g & 1) * 8;
            uint32_t aaddr = sb + (uint32_t)row * A_PITCH + (uint32_t)(k0 + (g >> 1) * 8) * 2;
            ldsm4(ahi[mt], aaddr + SM_A_HI);
            ldsm4(alo[mt], aaddr + SM_A_LO);
        }
        uint32_t bhi[4][2], blo[4][2];
#pragma unroll
        for (int nt = 0; nt < 4; nt++) {
            int nrow = nhalf * 32 + nt * 8 + lr;
            uint32_t baddr = sb + (uint32_t)nrow * A_PITCH + (uint32_t)(k0 + (g & 1) * 8) * 2;
            ldsm2(bhi[nt], baddr + SM_B_HI);
            ldsm2(blo[nt], baddr + SM_B_LO);
        }
#pragma unroll
        for (int mt = 0; mt < 2; mt++)
#pragma unroll
            for (int nt = 0; nt < 4; nt++) {
                mma16816(F.acc[mt][nt], ahi[mt], bhi[nt]);
                mma16816(F.acc[mt][nt], ahi[mt], blo[nt]);
                mma16816(F.acc[mt][nt], alo[mt], bhi[nt]);
            }
    }
}

// ---------------- h = x @ W_rel[r] for all r --------------------------------
extern "C" __global__ void __launch_bounds__(256, 2)
h_mma_kernel(int n) {
    extern __shared__ __align__(16) char sm[];
    const uint32_t sb = smem_u32(sm);
    const int tid = threadIdx.x, wid = tid >> 5, lane = tid & 31;
    const int mgroup = wid & 3, nhalf = wid >> 2;
    const int n0 = blockIdx.x * 128;

    // Load A (x hi/lo): 128 rows x 16 chunks of 16B, pitch 272
#pragma unroll
    for (int it = 0; it < 8; it++) {
        int idx = tid + it * 256;           // 0..2047
        int row = idx >> 4, c = idx & 15;
        int node = n0 + row;
        uint4 vh = make_uint4(0, 0, 0, 0), vl = vh;
        if (node < n) {
            vh = ((const uint4*)(g_xhi + (size_t)node * I_DIM))[c];
            vl = ((const uint4*)(g_xlo + (size_t)node * I_DIM))[c];
        }
        *(uint4*)(sm + SM_A_HI + row * A_PITCH + c * 16) = vh;
        *(uint4*)(sm + SM_A_LO + row * A_PITCH + c * 16) = vl;
    }

    Frag F;
    for (int r = 0; r < R_DIM; r++) {
        __syncthreads();
        // Load B_r (W hi/lo): 64 rows x 16 chunks, pitch 272
#pragma unroll
        for (int it = 0; it < 4; it++) {
            int idx = tid + it * 256;       // 0..1023
            int nr = idx >> 4, c = idx & 15;
            uint4 vh = ((const uint4*)(g_whi + ((size_t)r * O_DIM + nr) * I_DIM))[c];
            uint4 vl = ((const uint4*)(g_wlo + ((size_t)r * O_DIM + nr) * I_DIM))[c];
            *(uint4*)(sm + SM_B_HI + nr * A_PITCH + c * 16) = vh;
            *(uint4*)(sm + SM_B_LO + nr * A_PITCH + c * 16) = vl;
        }
        __syncthreads();

        mma_tile_compute(F, sb, mgroup, nhalf, lane);

        // epilogue: write h[node][r][col]
#pragma unroll
        for (int mt = 0; mt < 2; mt++) {
            int row = mgroup * 32 + mt * 16 + (lane >> 2);
#pragma unroll
            for (int nt = 0; nt < 4; nt++) {
                int col = nhalf * 32 + nt * 8 + (lane & 3) * 2;
                int nodeA = n0 + row, nodeB = n0 + row + 8;
                if (nodeA < n)
                    *(float2*)(g_h + (size_t)nodeA * RO + r * O_DIM + col) =
                        make_float2(F.acc[mt][nt][0], F.acc[mt][nt][1]);
                if (nodeB < n)
                    *(float2*)(g_h + (size_t)nodeB * RO + r * O_DIM + col) =
                        make_float2(F.acc[mt][nt][2], F.acc[mt][nt][3]);
            }
        }
    }
}

// ---------------- root: out = x @ W_root[type] + b_root[type] ---------------
extern "C" __global__ void __launch_bounds__(256, 2)
root_mma_kernel(const float* __restrict__ broot, float* __restrict__ out) {
    extern __shared__ __align__(16) char sm[];
    __shared__ int s_nid[128];
    const uint32_t sb = smem_u32(sm);
    const int tid = threadIdx.x, wid = tid >> 5, lane = tid & 31;
    const int mgroup = wid & 3, nhalf = wid >> 2;

    int b = blockIdx.x;
    int t = -1, tile = 0;
#pragma unroll
    for (int tt = 0; tt < T_DIM; tt++) {
        int lo = g_blockBase[tt], hi = g_blockBase[tt + 1];
        if (t < 0 && b >= lo && b < hi) { t = tt; tile = b - lo; }
    }
    if (t < 0) return;
    int row0 = g_offsets[t] + tile * 128;
    int rowEnd = g_offsets[t + 1];

    if (tid < 128) {
        int rr = row0 + tid;
        s_nid[tid] = (rr < rowEnd) ? g_order[rr] : -1;
    }
    __syncthreads();

#pragma unroll
    for (int it = 0; it < 8; it++) {
        int idx = tid + it * 256;
        int row = idx >> 4, c = idx & 15;
        int node = s_nid[row];
        uint4 vh = make_uint4(0, 0, 0, 0), vl = vh;
        if (node >= 0) {
            vh = ((const uint4*)(g_xhi + (size_t)node * I_DIM))[c];
            vl = ((const uint4*)(g_xlo + (size_t)node * I_DIM))[c];
        }
        *(uint4*)(sm + SM_A_HI + row * A_PITCH + c * 16) = vh;
        *(uint4*)(sm + SM_A_LO + row * A_PITCH + c * 16) = vl;
    }
#pragma unroll
    for (int it = 0; it < 4; it++) {
        int idx = tid + it * 256;
        int nr = idx >> 4, c = idx & 15;
        uint4 vh = ((const uint4*)(g_rwhi + ((size_t)t * O_DIM + nr) * I_DIM))[c];
        uint4 vl = ((const uint4*)(g_rwlo + ((size_t)t * O_DIM + nr) * I_DIM))[c];
        *(uint4*)(sm + SM_B_HI + nr * A_PITCH + c * 16) = vh;
        *(uint4*)(sm + SM_B_LO + nr * A_PITCH + c * 16) = vl;
    }
    __syncthreads();

    Frag F;
    mma_tile_compute(F, sb, mgroup, nhalf, lane);

#pragma unroll
    for (int mt = 0; mt < 2; mt++) {
        int row = mgroup * 32 + mt * 16 + (lane >> 2);
#pragma unroll
        for (int nt = 0; nt < 4; nt++) {
            int col = nhalf * 32 + nt * 8 + (lane & 3) * 2;
            float2 bias = *(const float2*)(broot + (size_t)t * O_DIM + col);
            int nodeA = s_nid[row], nodeB = s_nid[row + 8];
            if (nodeA >= 0)
                *(float2*)(out + (size_t)nodeA * O_DIM + col) =
                    make_float2(F.acc[mt][nt][0] + bias.x, F.acc[mt][nt][1] + bias.y);
            if (nodeB >= 0)
                *(float2*)(out + (size_t)nodeB * O_DIM + col) =
                    make_float2(F.acc[mt][nt][2] + bias.x, F.acc[mt][nt][3] + bias.y);
        }
    }
}

// ---------------- aggregate: warp per dst, no atomics -----------------------
// out[dst] += sum_e h[src_e, et_e] / cnt[dst, et_e] over this dst's edges.
__global__ void __launch_bounds__(256)
aggregate_kernel(float* __restrict__ out, int n) {
    int w = (blockIdx.x * 256 + threadIdx.x) >> 5;   // global warp id = dst
    int lane = threadIdx.x & 31;
    if (w >= n) return;
    int start = g_dstoff[w];
    int m = g_dstcnt[w];
    float2 acc = make_float2(0.f, 0.f);
    for (int j = 0; j < m; j++) {
        int packed = __ldg(&g_sorted[start + j]);
        int src = packed & 0xFFFFF;
        int et  = packed >> 20;
        float inv = 1.0f / (float)__ldg(&g_cnt[w * R_DIM + et]);
        float2 v = __ldg(((const float2*)(g_h + (size_t)src * RO + et * O_DIM)) + lane);
        acc.x += v.x * inv;
        acc.y += v.y * inv;
    }
    if (m > 0) {
        float2* op = ((float2*)(out + (size_t)w * O_DIM)) + lane;
        float2 cur = *op;
        cur.x += acc.x;
        cur.y += acc.y;
        *op = cur;
    }
}

// ---------------- launch ----------------------------------------------------
extern "C" void kernel_launch(void* const* d_in, const int* in_sizes, int n_in,
                              void* d_out, int out_size) {
    const float* x     = (const float*)d_in[0];
    const int*   ei    = (const int*)d_in[1];
    const int*   et    = (const int*)d_in[2];
    const int*   nt    = (const int*)d_in[3];
    const float* Wrel  = (const float*)d_in[4];
    const float* Wroot = (const float*)d_in[5];
    const float* broot = (const float*)d_in[6];
    float*       out   = (float*)d_out;

    int n = in_sizes[0] / I_DIM;
    int E = in_sizes[2];

    void *p_cnt = nullptr, *p_tcnt = nullptr, *p_dstcnt = nullptr;
    cudaGetSymbolAddress(&p_cnt, g_cnt);
    cudaGetSymbolAddress(&p_tcnt, g_tcnt);
    cudaGetSymbolAddress(&p_dstcnt, g_dstcnt);
    cudaMemsetAsync(p_cnt, 0, sizeof(int) * (size_t)n * R_DIM, 0);
    cudaMemsetAsync(p_tcnt, 0, sizeof(int) * T_DIM, 0);
    cudaMemsetAsync(p_dstcnt, 0, sizeof(int) * (size_t)n, 0);

    cudaFuncSetAttribute(h_mma_kernel,
                         cudaFuncAttributeMaxDynamicSharedMemorySize, SMEM_DYN);
    cudaFuncSetAttribute(root_mma_kernel,
                         cudaFuncAttributeMaxDynamicSharedMemorySize, SMEM_DYN);

    int total2 = n * (I_DIM / 2);
    convert_x_kernel<<<(total2 + 255) / 256, 256>>>(x, total2);
    convert_w_kernel<<<((R_DIM + T_DIM) * O_DIM * I_DIM + 255) / 256, 256>>>(Wrel, Wroot);

    int gemm_blocks = (n + 127) / 128;
    h_mma_kernel<<<gemm_blocks, 256, SMEM_DYN>>>(n);   // 6th op -> ncu -s 5 captures this

    // dst-CSR build
    edge_count_kernel<<<(E + 255) / 256, 256>>>(ei, et, E);
    int nblk = (n + 511) / 512;                        // <= 1024
    scan_blocks_kernel<<<nblk, 512>>>(n);
    scan_top_kernel<<<1, 1024>>>(nblk);
    scan_add_kernel<<<nblk, 512>>>(n);
    sort_scatter_kernel<<<(E + 255) / 256, 256>>>(ei, et, E);

    type_hist_kernel<<<(n + 255) / 256, 256>>>(nt, n);
    scan_kernel<<<1, 32>>>();
    type_scatter_kernel<<<(n + 255) / 256, 256>>>(nt, n);
    root_mma_kernel<<<gemm_blocks + T_DIM, 256, SMEM_DYN>>>(broot, out);

    aggregate_kernel<<<(n + 7) / 8, 256>>>(out, n);
}

// round 16
// speedup vs baseline: 2.0010x; 1.0618x over previous
#include <cuda_runtime.h>
#include <cuda_bf16.h>
#include <cuda_fp16.h>
#include <cstdint>

#define I_DIM 128
#define O_DIM 64
#define R_DIM 7
#define T_DIM 4
#define MAX_N 300000
#define MAX_E 4000000
#define RO (R_DIM * O_DIM)   // 448

// ---------------- scratch (device globals; no runtime allocation) ----------
__device__ __half        g_hh[(size_t)MAX_N * RO];    // ~268.8 MB, fp16 messages
__device__ int           g_cnt[MAX_N * R_DIM];
__device__ int           g_order[MAX_N];
__device__ int           g_tcnt[T_DIM];
__device__ int           g_offsets[T_DIM + 1];
__device__ int           g_cursor[T_DIM];
__device__ int           g_blockBase[T_DIM + 1];
__device__ int           g_dstcnt[MAX_N];             // per-dst edge count (from g_cnt)
__device__ int           g_dstoff[MAX_N];             // exclusive prefix
__device__ int           g_dstcur[MAX_N];             // scatter cursors
__device__ int           g_bsum[1024];                // block sums for scan
__device__ int           g_sorted[MAX_E];             // (et<<20)|src, dst-sorted
__device__ __nv_bfloat16 g_xhi[(size_t)MAX_N * I_DIM];
__device__ __nv_bfloat16 g_xlo[(size_t)MAX_N * I_DIM];
__device__ __nv_bfloat16 g_whi[R_DIM * O_DIM * I_DIM];   // [r][o][i] K-major
__device__ __nv_bfloat16 g_wlo[R_DIM * O_DIM * I_DIM];
__device__ __nv_bfloat16 g_rwhi[T_DIM * O_DIM * I_DIM];
__device__ __nv_bfloat16 g_rwlo[T_DIM * O_DIM * I_DIM];

// ---------------- warp-MMA helpers (sm_80+ base features, OK on sm_103) -----
__device__ __forceinline__ uint32_t smem_u32(const void* p) {
    uint32_t a;
    asm("{ .reg .u64 t; cvta.to.shared.u64 t, %1; cvt.u32.u64 %0, t; }"
        : "=r"(a) : "l"(p));
    return a;
}
__device__ __forceinline__ void ldsm4(uint32_t* r, uint32_t addr) {
    asm volatile("ldmatrix.sync.aligned.m8n8.x4.shared.b16 {%0,%1,%2,%3}, [%4];"
                 : "=r"(r[0]), "=r"(r[1]), "=r"(r[2]), "=r"(r[3]) : "r"(addr));
}
// NON-trans x2: B stored [n][k] (k contiguous) IS col-major k x n; plain
// ldmatrix yields the b-fragment (thread t: consecutive k at fixed n=t/4).
__device__ __forceinline__ void ldsm2(uint32_t* r, uint32_t addr) {
    asm volatile("ldmatrix.sync.aligned.m8n8.x2.shared.b16 {%0,%1}, [%2];"
                 : "=r"(r[0]), "=r"(r[1]) : "r"(addr));
}
__device__ __forceinline__ void mma16816(float* c, const uint32_t* a, const uint32_t* b) {
    asm volatile(
        "mma.sync.aligned.m16n8k16.row.col.f32.bf16.bf16.f32 "
        "{%0,%1,%2,%3}, {%4,%5,%6,%7}, {%8,%9}, {%0,%1,%2,%3};"
        : "+f"(c[0]), "+f"(c[1]), "+f"(c[2]), "+f"(c[3])
        : "r"(a[0]), "r"(a[1]), "r"(a[2]), "r"(a[3]), "r"(b[0]), "r"(b[1]));
}

// smem layout (bytes): rows are 128 bf16 = 256B data; pitch 272 = 256+16 pad.
#define A_PITCH 272
#define SM_A_HI 0
#define SM_A_LO 34816              // 128*272
#define SM_B_HI 69632
#define SM_B_LO 87040              // +64*272
#define SMEM_DYN 104448            // +64*272

// ---------------- conversion kernels ----------------------------------------
__global__ void convert_x_kernel(const float* __restrict__ x, int total2) {
    int i = blockIdx.x * 256 + threadIdx.x;
    if (i < total2) {
        float2 v = ((const float2*)x)[i];
        __nv_bfloat16 h0 = __float2bfloat16(v.x);
        __nv_bfloat16 h1 = __float2bfloat16(v.y);
        __nv_bfloat162 hh; hh.x = h0; hh.y = h1;
        __nv_bfloat162 ll;
        ll.x = __float2bfloat16(v.x - __bfloat162float(h0));
        ll.y = __float2bfloat16(v.y - __bfloat162float(h1));
        ((__nv_bfloat162*)g_xhi)[i] = hh;
        ((__nv_bfloat162*)g_xlo)[i] = ll;
    }
}

__global__ void convert_w_kernel(const float* __restrict__ Wrel,
                                 const float* __restrict__ Wroot) {
    int i = blockIdx.x * 256 + threadIdx.x;
    if (i >= (R_DIM + T_DIM) * O_DIM * I_DIM) return;
    int grp = i >> 13;            // 8192 = 64*128
    int rem = i & 8191;
    int nrow = rem >> 7;          // O index
    int k = rem & 127;            // I index
    float v;
    if (grp < R_DIM) v = Wrel[((size_t)grp * I_DIM + k) * O_DIM + nrow];
    else             v = Wroot[((size_t)(grp - R_DIM) * I_DIM + k) * O_DIM + nrow];
    __nv_bfloat16 h = __float2bfloat16(v);
    __nv_bfloat16 l = __float2bfloat16(v - __bfloat162float(h));
    if (grp < R_DIM) { g_whi[i] = h; g_wlo[i] = l; }
    else { g_rwhi[(grp - R_DIM) * 8192 + rem] = h; g_rwlo[(grp - R_DIM) * 8192 + rem] = l; }
}

// ---------------- small prep kernels ---------------------------------------
__global__ void edge_count_kernel(const int* __restrict__ ei,
                                  const int* __restrict__ etype, int E) {
    int e = blockIdx.x * 256 + threadIdx.x;
    if (e < E) atomicAdd(&g_cnt[ei[E + e] * R_DIM + etype[e]], 1);
}

__global__ void type_hist_kernel(const int* __restrict__ nt, int n) {
    __shared__ int s[T_DIM];
    if (threadIdx.x < T_DIM) s[threadIdx.x] = 0;
    __syncthreads();
    int i = blockIdx.x * 256 + threadIdx.x;
    if (i < n) atomicAdd(&s[nt[i]], 1);
    __syncthreads();
    if (threadIdx.x < T_DIM) atomicAdd(&g_tcnt[threadIdx.x], s[threadIdx.x]);
}

__global__ void scan_kernel() {
    if (threadIdx.x == 0 && blockIdx.x == 0) {
        int off = 0, bb = 0;
        g_offsets[0] = 0;
        g_blockBase[0] = 0;
        for (int t = 0; t < T_DIM; t++) {
            int c = g_tcnt[t];
            g_cursor[t] = off;
            off += c;
            g_offsets[t + 1] = off;
            bb += (c + 127) >> 7;
            g_blockBase[t + 1] = bb;
        }
    }
}

__global__ void type_scatter_kernel(const int* __restrict__ nt, int n) {
    __shared__ int s_cnt[T_DIM];
    __shared__ int s_base[T_DIM];
    if (threadIdx.x < T_DIM) s_cnt[threadIdx.x] = 0;
    __syncthreads();
    int i = blockIdx.x * 256 + threadIdx.x;
    int t = 0, r = 0;
    bool valid = (i < n);
    if (valid) { t = nt[i]; r = atomicAdd(&s_cnt[t], 1); }
    __syncthreads();
    if (threadIdx.x < T_DIM)
        s_base[threadIdx.x] = atomicAdd(&g_cursor[threadIdx.x], s_cnt[threadIdx.x]);
    __syncthreads();
    if (valid) g_order[s_base[t] + r] = i;
}

// ---------------- dst-CSR: block scan over per-dst counts -------------------
// dstcnt derived from g_cnt (sum over relations) - no per-edge atomic needed.
__global__ void scan_blocks_kernel(int n) {
    __shared__ int wsum[16];
    int i = blockIdx.x * 512 + threadIdx.x;
    int lane = threadIdx.x & 31, wid = threadIdx.x >> 5;
    int v = 0;
    if (i < n) {
#pragma unroll
        for (int r = 0; r < R_DIM; r++) v += g_cnt[i * R_DIM + r];
        g_dstcnt[i] = v;
    }
    int x = v;
#pragma unroll
    for (int d = 1; d < 32; d <<= 1) {
        int y = __shfl_up_sync(0xFFFFFFFF, x, d);
        if (lane >= d) x += y;
    }
    if (lane == 31) wsum[wid] = x;
    __syncthreads();
    if (wid == 0) {
        int s = (lane < 16) ? wsum[lane] : 0;
#pragma unroll
        for (int d = 1; d < 16; d <<= 1) {
            int y = __shfl_up_sync(0xFFFFFFFF, s, d);
            if (lane >= d) s += y;
        }
        if (lane < 16) wsum[lane] = s;
    }
    __syncthreads();
    int base = (wid > 0) ? wsum[wid - 1] : 0;
    if (i < n) g_dstoff[i] = base + x - v;          // exclusive within block
    if (threadIdx.x == 511) g_bsum[blockIdx.x] = base + x;  // block total
}

__global__ void scan_top_kernel(int nblk) {
    __shared__ int wsum[32];
    int i = threadIdx.x;                   // single block, 1024 threads
    int lane = i & 31, wid = i >> 5;
    int v = (i < nblk) ? g_bsum[i] : 0;
    int x = v;
#pragma unroll
    for (int d = 1; d < 32; d <<= 1) {
        int y = __shfl_up_sync(0xFFFFFFFF, x, d);
        if (lane >= d) x += y;
    }
    if (lane == 31) wsum[wid] = x;
    __syncthreads();
    if (wid == 0) {
        int s = wsum[lane];
#pragma unroll
        for (int d = 1; d < 32; d <<= 1) {
            int y = __shfl_up_sync(0xFFFFFFFF, s, d);
            if (lane >= d) s += y;
        }
        wsum[lane] = s;
    }
    __syncthreads();
    int base = (wid > 0) ? wsum[wid - 1] : 0;
    if (i < nblk) g_bsum[i] = base + x - v;         // exclusive block offsets
}

__global__ void scan_add_kernel(int n) {
    int i = blockIdx.x * 512 + threadIdx.x;
    if (i < n) {
        int off = g_dstoff[i] + g_bsum[i >> 9];
        g_dstoff[i] = off;
        g_dstcur[i] = off;
    }
}

__global__ void sort_scatter_kernel(const int* __restrict__ ei,
                                    const int* __restrict__ etype, int E) {
    int e = blockIdx.x * 256 + threadIdx.x;
    if (e < E) {
        int dst = ei[E + e];
        int pos = atomicAdd(&g_dstcur[dst], 1);
        g_sorted[pos] = (etype[e] << 20) | ei[e];   // src < 2^20 fits
    }
}

// ---------------- shared device helpers for the MMA GEMMs -------------------
// Per block: 128 M-rows x 64 N-cols x K=128. 8 warps: (wid&3)=M-group of 32
// rows, (wid>>2)=N-half of 32 cols. Per warp: 2 m16 tiles x 4 n8 tiles.
// fp32 emulation: acc += Ahi*Bhi + Ahi*Blo + Alo*Bhi (bf16 mma, f32 accum).
struct Frag { float acc[2][4][4]; };

__device__ __forceinline__ void mma_tile_compute(Frag& F, uint32_t sb,
                                                 int mgroup, int nhalf, int lane) {
#pragma unroll
    for (int mt = 0; mt < 2; mt++)
#pragma unroll
        for (int nt = 0; nt < 4; nt++)
#pragma unroll
            for (int q = 0; q < 4; q++) F.acc[mt][nt][q] = 0.f;

    const int lr = lane & 7, g = lane >> 3;
#pragma unroll
    for (int ks = 0; ks < 8; ks++) {
        const int k0 = ks * 16;
        uint32_t ahi[2][4], alo[2][4];
#pragma unroll
        for (int mt = 0; mt < 2; mt++) {
            int row = mgroup * 32 + mt * 16 + lr + (g & 1) * 8;
            uint32_t aaddr = sb + (uint32_t)row * A_PITCH + (uint32_t)(k0 + (g >> 1) * 8) * 2;
            ldsm4(ahi[mt], aaddr + SM_A_HI);
            ldsm4(alo[mt], aaddr + SM_A_LO);
        }
        uint32_t bhi[4][2], blo[4][2];
#pragma unroll
        for (int nt = 0; nt < 4; nt++) {
            int nrow = nhalf * 32 + nt * 8 + lr;
            uint32_t baddr = sb + (uint32_t)nrow * A_PITCH + (uint32_t)(k0 + (g & 1) * 8) * 2;
            ldsm2(bhi[nt], baddr + SM_B_HI);
            ldsm2(blo[nt], baddr + SM_B_LO);
        }
#pragma unroll
        for (int mt = 0; mt < 2; mt++)
#pragma unroll
            for (int nt = 0; nt < 4; nt++) {
                mma16816(F.acc[mt][nt], ahi[mt], bhi[nt]);
                mma16816(F.acc[mt][nt], ahi[mt], blo[nt]);
                mma16816(F.acc[mt][nt], alo[mt], bhi[nt]);
            }
    }
}

// ---------------- h = x @ W_rel[r] for all r (fp16 output) ------------------
extern "C" __global__ void __launch_bounds__(256, 2)
h_mma_kernel(int n) {
    extern __shared__ __align__(16) char sm[];
    const uint32_t sb = smem_u32(sm);
    const int tid = threadIdx.x, wid = tid >> 5, lane = tid & 31;
    const int mgroup = wid & 3, nhalf = wid >> 2;
    const int n0 = blockIdx.x * 128;

    // Load A (x hi/lo): 128 rows x 16 chunks of 16B, pitch 272
#pragma unroll
    for (int it = 0; it < 8; it++) {
        int idx = tid + it * 256;           // 0..2047
        int row = idx >> 4, c = idx & 15;
        int node = n0 + row;
        uint4 vh = make_uint4(0, 0, 0, 0), vl = vh;
        if (node < n) {
            vh = ((const uint4*)(g_xhi + (size_t)node * I_DIM))[c];
            vl = ((const uint4*)(g_xlo + (size_t)node * I_DIM))[c];
        }
        *(uint4*)(sm + SM_A_HI + row * A_PITCH + c * 16) = vh;
        *(uint4*)(sm + SM_A_LO + row * A_PITCH + c * 16) = vl;
    }

    Frag F;
    for (int r = 0; r < R_DIM; r++) {
        __syncthreads();
        // Load B_r (W hi/lo): 64 rows x 16 chunks, pitch 272
#pragma unroll
        for (int it = 0; it < 4; it++) {
            int idx = tid + it * 256;       // 0..1023
            int nr = idx >> 4, c = idx & 15;
            uint4 vh = ((const uint4*)(g_whi + ((size_t)r * O_DIM + nr) * I_DIM))[c];
            uint4 vl = ((const uint4*)(g_wlo + ((size_t)r * O_DIM + nr) * I_DIM))[c];
            *(uint4*)(sm + SM_B_HI + nr * A_PITCH + c * 16) = vh;
            *(uint4*)(sm + SM_B_LO + nr * A_PITCH + c * 16) = vl;
        }
        __syncthreads();

        mma_tile_compute(F, sb, mgroup, nhalf, lane);

        // epilogue: write h[node][r][col] as fp16
#pragma unroll
        for (int mt = 0; mt < 2; mt++) {
            int row = mgroup * 32 + mt * 16 + (lane >> 2);
#pragma unroll
            for (int nt = 0; nt < 4; nt++) {
                int col = nhalf * 32 + nt * 8 + (lane & 3) * 2;
                int nodeA = n0 + row, nodeB = n0 + row + 8;
                if (nodeA < n)
                    *(__half2*)(g_hh + (size_t)nodeA * RO + r * O_DIM + col) =
                        __floats2half2_rn(F.acc[mt][nt][0], F.acc[mt][nt][1]);
                if (nodeB < n)
                    *(__half2*)(g_hh + (size_t)nodeB * RO + r * O_DIM + col) =
                        __floats2half2_rn(F.acc[mt][nt][2], F.acc[mt][nt][3]);
            }
        }
    }
}

// ---------------- root: out = x @ W_root[type] + b_root[type] ---------------
extern "C" __global__ void __launch_bounds__(256, 2)
root_mma_kernel(const float* __restrict__ broot, float* __restrict__ out) {
    extern __shared__ __align__(16) char sm[];
    __shared__ int s_nid[128];
    const uint32_t sb = smem_u32(sm);
    const int tid = threadIdx.x, wid = tid >> 5, lane = tid & 31;
    const int mgroup = wid & 3, nhalf = wid >> 2;

    int b = blockIdx.x;
    int t = -1, tile = 0;
#pragma unroll
    for (int tt = 0; tt < T_DIM; tt++) {
        int lo = g_blockBase[tt], hi = g_blockBase[tt + 1];
        if (t < 0 && b >= lo && b < hi) { t = tt; tile = b - lo; }
    }
    if (t < 0) return;
    int row0 = g_offsets[t] + tile * 128;
    int rowEnd = g_offsets[t + 1];

    if (tid < 128) {
        int rr = row0 + tid;
        s_nid[tid] = (rr < rowEnd) ? g_order[rr] : -1;
    }
    __syncthreads();

#pragma unroll
    for (int it = 0; it < 8; it++) {
        int idx = tid + it * 256;
        int row = idx >> 4, c = idx & 15;
        int node = s_nid[row];
        uint4 vh = make_uint4(0, 0, 0, 0), vl = vh;
        if (node >= 0) {
            vh = ((const uint4*)(g_xhi + (size_t)node * I_DIM))[c];
            vl = ((const uint4*)(g_xlo + (size_t)node * I_DIM))[c];
        }
        *(uint4*)(sm + SM_A_HI + row * A_PITCH + c * 16) = vh;
        *(uint4*)(sm + SM_A_LO + row * A_PITCH + c * 16) = vl;
    }
#pragma unroll
    for (int it = 0; it < 4; it++) {
        int idx = tid + it * 256;
        int nr = idx >> 4, c = idx & 15;
        uint4 vh = ((const uint4*)(g_rwhi + ((size_t)t * O_DIM + nr) * I_DIM))[c];
        uint4 vl = ((const uint4*)(g_rwlo + ((size_t)t * O_DIM + nr) * I_DIM))[c];
        *(uint4*)(sm + SM_B_HI + nr * A_PITCH + c * 16) = vh;
        *(uint4*)(sm + SM_B_LO + nr * A_PITCH + c * 16) = vl;
    }
    __syncthreads();

    Frag F;
    mma_tile_compute(F, sb, mgroup, nhalf, lane);

#pragma unroll
    for (int mt = 0; mt < 2; mt++) {
        int row = mgroup * 32 + mt * 16 + (lane >> 2);
#pragma unroll
        for (int nt = 0; nt < 4; nt++) {
            int col = nhalf * 32 + nt * 8 + (lane & 3) * 2;
            float2 bias = *(const float2*)(broot + (size_t)t * O_DIM + col);
            int nodeA = s_nid[row], nodeB = s_nid[row + 8];
            if (nodeA >= 0)
                *(float2*)(out + (size_t)nodeA * O_DIM + col) =
                    make_float2(F.acc[mt][nt][0] + bias.x, F.acc[mt][nt][1] + bias.y);
            if (nodeB >= 0)
                *(float2*)(out + (size_t)nodeB * O_DIM + col) =
                    make_float2(F.acc[mt][nt][2] + bias.x, F.acc[mt][nt][3] + bias.y);
        }
    }
}

// ---------------- aggregate: warp per dst, no atomics, fp16 gather ----------
// out[dst] += sum_e h[src_e, et_e] / cnt[dst, et_e] over this dst's edges.
__global__ void __launch_bounds__(256)
aggregate_kernel(float* __restrict__ out, int n) {
    int w = (blockIdx.x * 256 + threadIdx.x) >> 5;   // global warp id = dst
    int lane = threadIdx.x & 31;
    if (w >= n) return;
    int start = g_dstoff[w];
    int m = g_dstcnt[w];
    float2 acc = make_float2(0.f, 0.f);
    for (int j = 0; j < m; j++) {
        int packed = __ldg(&g_sorted[start + j]);
        int src = packed & 0xFFFFF;
        int et  = packed >> 20;
        float inv = 1.0f / (float)__ldg(&g_cnt[w * R_DIM + et]);
        __half2 v = __ldg(((const __half2*)(g_hh + (size_t)src * RO + et * O_DIM)) + lane);
        float2 f = __half22float2(v);
        acc.x += f.x * inv;
        acc.y += f.y * inv;
    }
    if (m > 0) {
        float2* op = ((float2*)(out + (size_t)w * O_DIM)) + lane;
        float2 cur = *op;
        cur.x += acc.x;
        cur.y += acc.y;
        *op = cur;
    }
}

// ---------------- launch ----------------------------------------------------
extern "C" void kernel_launch(void* const* d_in, const int* in_sizes, int n_in,
                              void* d_out, int out_size) {
    const float* x     = (const float*)d_in[0];
    const int*   ei    = (const int*)d_in[1];
    const int*   et    = (const int*)d_in[2];
    const int*   nt    = (const int*)d_in[3];
    const float* Wrel  = (const float*)d_in[4];
    const float* Wroot = (const float*)d_in[5];
    const float* broot = (const float*)d_in[6];
    float*       out   = (float*)d_out;

    int n = in_sizes[0] / I_DIM;
    int E = in_sizes[2];

    void *p_cnt = nullptr, *p_tcnt = nullptr;
    cudaGetSymbolAddress(&p_cnt, g_cnt);
    cudaGetSymbolAddress(&p_tcnt, g_tcnt);
    cudaMemsetAsync(p_cnt, 0, sizeof(int) * (size_t)n * R_DIM, 0);
    cudaMemsetAsync(p_tcnt, 0, sizeof(int) * T_DIM, 0);

    cudaFuncSetAttribute(h_mma_kernel,
                         cudaFuncAttributeMaxDynamicSharedMemorySize, SMEM_DYN);
    cudaFuncSetAttribute(root_mma_kernel,
                         cudaFuncAttributeMaxDynamicSharedMemorySize, SMEM_DYN);

    int total2 = n * (I_DIM / 2);
    convert_x_kernel<<<(total2 + 255) / 256, 256>>>(x, total2);
    convert_w_kernel<<<((R_DIM + T_DIM) * O_DIM * I_DIM + 255) / 256, 256>>>(Wrel, Wroot);

    int gemm_blocks = (n + 127) / 128;
    h_mma_kernel<<<gemm_blocks, 256, SMEM_DYN>>>(n);

    // dst-CSR build (dstcnt derived from g_cnt inside scan_blocks)
    edge_count_kernel<<<(E + 255) / 256, 256>>>(ei, et, E);
    int nblk = (n + 511) / 512;                        // <= 1024
    scan_blocks_kernel<<<nblk, 512>>>(n);
    scan_top_kernel<<<1, 1024>>>(nblk);
    scan_add_kernel<<<nblk, 512>>>(n);
    sort_scatter_kernel<<<(E + 255) / 256, 256>>>(ei, et, E);

    type_hist_kernel<<<(n + 255) / 256, 256>>>(nt, n);
    scan_kernel<<<1, 32>>>();
    type_scatter_kernel<<<(n + 255) / 256, 256>>>(nt, n);
    root_mma_kernel<<<gemm_blocks + T_DIM, 256, SMEM_DYN>>>(broot, out);

    aggregate_kernel<<<(n + 7) / 8, 256>>>(out, n);
}